// round 1
// baseline (speedup 1.0000x reference)
#include <cuda_runtime.h>
#include <mma.h>
#include <cstdint>
#include <cstddef>

using namespace nvcuda;

// Problem constants (fixed by the dataset)
#define DMODEL 1024
#define DFF    4096
#define NHEADS 16
#define DKH    64
#define SEQ    1024
#define MAXB   8

// ---------------- scratch (static __device__ — no allocation allowed) ----------------
__device__ float g_x1[(size_t)MAXB * SEQ * DMODEL];               // x1 / x2
__device__ float g_q [(size_t)MAXB * SEQ * DMODEL];
__device__ float g_k [(size_t)MAXB * SEQ * DMODEL];
__device__ float g_v [(size_t)MAXB * SEQ * DMODEL];
__device__ float g_at[(size_t)MAXB * SEQ * DMODEL];               // attention output (pre O-proj)
__device__ float g_h [(size_t)MAXB * SEQ * DFF];                  // FFN hidden
__device__ float g_s [(size_t)MAXB * NHEADS * SEQ * SEQ];         // scores / probs (512 MB)

// ---------------- helpers ----------------
__device__ __forceinline__ void cp16(float* s, const float* g) {
    uint32_t sa = (uint32_t)__cvta_generic_to_shared(s);
    asm volatile("cp.async.cg.shared.global [%0], [%1], 16;\n" :: "r"(sa), "l"(g));
}

struct GemmP {
    const float* A; const float* B; float* C;
    const float* bias; const float* res; const int* mask;
    int lda, ldb, ldc, K, H, maskL;
    long long sAo, sAi, sBo, sBi, sCo, sCi;
    float scale;
};

// EPI: 0 = none, 1 = +bias, 2 = relu(+bias), 3 = +bias +residual, 4 = *scale + mask
template<int BM, int BN, int BK, int WM, int WN, bool TRANSB, int EPI>
__global__ void __launch_bounds__(256) gemm_k(GemmP p) {
    constexpr int TH  = 256;
    constexpr int AST = BK + 8;                       // A smem row stride
    constexpr int BROW = TRANSB ? BN : BK;
    constexpr int BST  = TRANSB ? (BK + 8) : (BN + 8);
    constexpr int ASZ = BM * AST, BSZ = BROW * BST;
    extern __shared__ float sm[];
    float* As[2] = { sm, sm + ASZ };
    float* Bs[2] = { sm + 2 * ASZ, sm + 2 * ASZ + BSZ };
    float* Cs = sm;                                   // reused for epilogue staging

    const int tid = threadIdx.x, warp = tid >> 5;
    constexpr int WARPS_M = BM / WM, WARPS_N = BN / WN;
    static_assert(WARPS_M * WARPS_N == 8, "need 8 warps");
    const int wm = warp % WARPS_M, wn = warp / WARPS_M;
    constexpr int FM = WM / 16, FN = WN / 16;

    const int z = blockIdx.z, outer = z / p.H, inner = z - outer * p.H;
    const float* Ag = p.A + outer * p.sAo + inner * p.sAi + (long long)blockIdx.y * BM * p.lda;
    const float* Bg = p.B + outer * p.sBo + inner * p.sBi
                    + (TRANSB ? (long long)blockIdx.x * BN * p.ldb : (long long)blockIdx.x * BN);
    float* Cg = p.C + outer * p.sCo + inner * p.sCi;

    wmma::fragment<wmma::accumulator, 16, 16, 8, float> acc[FM][FN];
    #pragma unroll
    for (int i = 0; i < FM; i++)
        #pragma unroll
        for (int j = 0; j < FN; j++) wmma::fill_fragment(acc[i][j], 0.0f);

    const int KT = p.K / BK;

    auto load_tiles = [&](int kt, int buf) {
        {
            const float* src = Ag + kt * BK;
            #pragma unroll
            for (int i = 0; i < BM * BK / (4 * TH); i++) {
                int e = (i * TH + tid) * 4, r = e / BK, c = e % BK;
                cp16(&As[buf][r * AST + c], src + (long long)r * p.lda + c);
            }
        }
        if (TRANSB) {
            const float* src = Bg + kt * BK;
            #pragma unroll
            for (int i = 0; i < BN * BK / (4 * TH); i++) {
                int e = (i * TH + tid) * 4, r = e / BK, c = e % BK;
                cp16(&Bs[buf][r * BST + c], src + (long long)r * p.ldb + c);
            }
        } else {
            const float* src = Bg + (long long)kt * BK * p.ldb;
            #pragma unroll
            for (int i = 0; i < BK * BN / (4 * TH); i++) {
                int e = (i * TH + tid) * 4, r = e / BN, c = e % BN;
                cp16(&Bs[buf][r * BST + c], src + (long long)r * p.ldb + c);
            }
        }
        asm volatile("cp.async.commit_group;\n");
    };

    load_tiles(0, 0);
    for (int kt = 0; kt < KT; kt++) {
        int cur = kt & 1;
        if (kt + 1 < KT) { load_tiles(kt + 1, cur ^ 1); asm volatile("cp.async.wait_group 1;\n"); }
        else             { asm volatile("cp.async.wait_group 0;\n"); }
        __syncthreads();
        #pragma unroll
        for (int kk = 0; kk < BK / 8; kk++) {
            wmma::fragment<wmma::matrix_a, 16, 16, 8, wmma::precision::tf32, wmma::row_major> af[FM];
            #pragma unroll
            for (int i = 0; i < FM; i++) {
                wmma::load_matrix_sync(af[i], &As[cur][(wm * WM + i * 16) * AST + kk * 8], AST);
                #pragma unroll
                for (int t = 0; t < af[i].num_elements; t++)
                    af[i].x[t] = wmma::__float_to_tf32(af[i].x[t]);
            }
            #pragma unroll
            for (int j = 0; j < FN; j++) {
                if constexpr (TRANSB) {
                    wmma::fragment<wmma::matrix_b, 16, 16, 8, wmma::precision::tf32, wmma::col_major> bf;
                    wmma::load_matrix_sync(bf, &Bs[cur][(wn * WN + j * 16) * BST + kk * 8], BST);
                    #pragma unroll
                    for (int t = 0; t < bf.num_elements; t++) bf.x[t] = wmma::__float_to_tf32(bf.x[t]);
                    #pragma unroll
                    for (int i = 0; i < FM; i++) wmma::mma_sync(acc[i][j], af[i], bf, acc[i][j]);
                } else {
                    wmma::fragment<wmma::matrix_b, 16, 16, 8, wmma::precision::tf32, wmma::row_major> bf;
                    wmma::load_matrix_sync(bf, &Bs[cur][(kk * 8) * BST + wn * WN + j * 16], BST);
                    #pragma unroll
                    for (int t = 0; t < bf.num_elements; t++) bf.x[t] = wmma::__float_to_tf32(bf.x[t]);
                    #pragma unroll
                    for (int i = 0; i < FM; i++) wmma::mma_sync(acc[i][j], af[i], bf, acc[i][j]);
                }
            }
        }
        __syncthreads();
    }

    // epilogue: stage accumulators through smem, then elementwise + vectorized store
    #pragma unroll
    for (int i = 0; i < FM; i++)
        #pragma unroll
        for (int j = 0; j < FN; j++)
            wmma::store_matrix_sync(&Cs[(wm * WM + i * 16) * (BN + 8) + wn * WN + j * 16],
                                    acc[i][j], BN + 8, wmma::mem_row_major);
    __syncthreads();

    const int gr0 = blockIdx.y * BM, gc0 = blockIdx.x * BN;
    #pragma unroll
    for (int it = 0; it < BM * BN / (4 * TH); ++it) {
        int e = (it * TH + tid) * 4, r = e / BN, c = e % BN;
        float4 vv = *(float4*)&Cs[r * (BN + 8) + c];
        int gr = gr0 + r, gc = gc0 + c;
        if constexpr (EPI == 1 || EPI == 2 || EPI == 3) {
            float4 bb = *(const float4*)&p.bias[gc];
            vv.x += bb.x; vv.y += bb.y; vv.z += bb.z; vv.w += bb.w;
        }
        if constexpr (EPI == 2) {
            vv.x = fmaxf(vv.x, 0.f); vv.y = fmaxf(vv.y, 0.f);
            vv.z = fmaxf(vv.z, 0.f); vv.w = fmaxf(vv.w, 0.f);
        }
        if constexpr (EPI == 3) {
            const float* Rg = p.res + outer * p.sCo + inner * p.sCi;
            float4 rr = *(const float4*)&Rg[(long long)gr * p.ldc + gc];
            vv.x += rr.x; vv.y += rr.y; vv.z += rr.z; vv.w += rr.w;
        }
        if constexpr (EPI == 4) {
            vv.x *= p.scale; vv.y *= p.scale; vv.z *= p.scale; vv.w *= p.scale;
            const int* mk = p.mask + (long long)outer * p.maskL;
            if (mk[gc + 0] == 0) vv.x = -1e9f;
            if (mk[gc + 1] == 0) vv.y = -1e9f;
            if (mk[gc + 2] == 0) vv.z = -1e9f;
            if (mk[gc + 3] == 0) vv.w = -1e9f;
        }
        *(float4*)&Cg[(long long)gr * p.ldc + gc] = vv;
    }
}

// ---------------- LayerNorm: one block per row, D=1024, 256 threads ----------------
__global__ void ln_kernel(const float* __restrict__ x, const float* __restrict__ g,
                          const float* __restrict__ b, float* __restrict__ out) {
    __shared__ float red[8];
    __shared__ float sbc;
    const int row = blockIdx.x, tid = threadIdx.x;
    const float4 v = ((const float4*)(x + (size_t)row * 1024))[tid];
    float s = v.x + v.y + v.z + v.w;
    #pragma unroll
    for (int o = 16; o > 0; o >>= 1) s += __shfl_xor_sync(0xffffffffu, s, o);
    if ((tid & 31) == 0) red[tid >> 5] = s;
    __syncthreads();
    if (tid == 0) { float t = 0.f; for (int i = 0; i < 8; i++) t += red[i]; sbc = t; }
    __syncthreads();
    const float mu = sbc * (1.0f / 1024.0f);
    float dx0 = v.x - mu, dx1 = v.y - mu, dx2 = v.z - mu, dx3 = v.w - mu;
    float s2 = dx0 * dx0 + dx1 * dx1 + dx2 * dx2 + dx3 * dx3;
    #pragma unroll
    for (int o = 16; o > 0; o >>= 1) s2 += __shfl_xor_sync(0xffffffffu, s2, o);
    if ((tid & 31) == 0) red[tid >> 5] = s2;
    __syncthreads();
    if (tid == 0) { float t = 0.f; for (int i = 0; i < 8; i++) t += red[i]; sbc = t; }
    __syncthreads();
    const float rs = rsqrtf(sbc * (1.0f / 1024.0f) + 1e-6f);
    const float4 gg = ((const float4*)g)[tid];
    const float4 bb = ((const float4*)b)[tid];
    float4 o;
    o.x = dx0 * rs * gg.x + bb.x; o.y = dx1 * rs * gg.y + bb.y;
    o.z = dx2 * rs * gg.z + bb.z; o.w = dx3 * rs * gg.w + bb.w;
    ((float4*)(out + (size_t)row * 1024))[tid] = o;
}

// ---------------- row softmax over 1024 columns ----------------
__global__ void softmax_kernel(float* __restrict__ S) {
    __shared__ float red[8];
    __shared__ float sbc;
    const size_t row = blockIdx.x;
    const int tid = threadIdx.x;
    float4* ptr = (float4*)(S + row * 1024);
    float4 v = ptr[tid];
    float m = fmaxf(fmaxf(v.x, v.y), fmaxf(v.z, v.w));
    #pragma unroll
    for (int o = 16; o > 0; o >>= 1) m = fmaxf(m, __shfl_xor_sync(0xffffffffu, m, o));
    if ((tid & 31) == 0) red[tid >> 5] = m;
    __syncthreads();
    if (tid == 0) { float t = -3.4e38f; for (int i = 0; i < 8; i++) t = fmaxf(t, red[i]); sbc = t; }
    __syncthreads();
    const float M = sbc;
    float e0 = expf(v.x - M), e1 = expf(v.y - M), e2 = expf(v.z - M), e3 = expf(v.w - M);
    float s = e0 + e1 + e2 + e3;
    #pragma unroll
    for (int o = 16; o > 0; o >>= 1) s += __shfl_xor_sync(0xffffffffu, s, o);
    if ((tid & 31) == 0) red[tid >> 5] = s;
    __syncthreads();
    if (tid == 0) { float t = 0.f; for (int i = 0; i < 8; i++) t += red[i]; sbc = t; }
    __syncthreads();
    const float inv = 1.0f / sbc;
    ptr[tid] = make_float4(e0 * inv, e1 * inv, e2 * inv, e3 * inv);
}

// ---------------- host ----------------
template<int BM, int BN, int BK, bool TRANSB>
constexpr int smemBytes() {
    int a = BM * (BK + 8);
    int b = (TRANSB ? BN : BK) * (TRANSB ? (BK + 8) : (BN + 8));
    int m = 2 * (a + b);
    int e = BM * (BN + 8);
    return (m > e ? m : e) * 4;
}

extern "C" void kernel_launch(void* const* d_in, const int* in_sizes, int n_in,
                              void* d_out, int out_size) {
    const float* x    = (const float*)d_in[0];
    const int*   em   = (const int*)  d_in[1];
    const float* ln1g = (const float*)d_in[2];
    const float* ln1b = (const float*)d_in[3];
    const float* Wq   = (const float*)d_in[4];
    const float* bq   = (const float*)d_in[5];
    const float* Wk   = (const float*)d_in[6];
    const float* bk   = (const float*)d_in[7];
    const float* Wv   = (const float*)d_in[8];
    const float* bv   = (const float*)d_in[9];
    const float* Wo   = (const float*)d_in[10];
    const float* bo   = (const float*)d_in[11];
    const float* ln2g = (const float*)d_in[12];
    const float* ln2b = (const float*)d_in[13];
    const float* W1   = (const float*)d_in[14];
    const float* b1   = (const float*)d_in[15];
    const float* W2   = (const float*)d_in[16];
    const float* b2   = (const float*)d_in[17];
    float* out = (float*)d_out;

    const int M  = in_sizes[0] / DMODEL;   // B*L = 8192
    const int Bb = M / SEQ;                // batch = 8

    float *x1, *q, *k, *v, *at, *h, *s;
    cudaGetSymbolAddress((void**)&x1, g_x1);
    cudaGetSymbolAddress((void**)&q,  g_q);
    cudaGetSymbolAddress((void**)&k,  g_k);
    cudaGetSymbolAddress((void**)&v,  g_v);
    cudaGetSymbolAddress((void**)&at, g_at);
    cudaGetSymbolAddress((void**)&h,  g_h);
    cudaGetSymbolAddress((void**)&s,  g_s);

    constexpr int SM_NN = smemBytes<128, 128, 32, false>();
    constexpr int SM_NT = smemBytes<128, 128, 32, true>();
    constexpr int SM_PV = smemBytes<128, 64, 32, false>();
    cudaFuncSetAttribute(gemm_k<128,128,32,64,32,false,1>, cudaFuncAttributeMaxDynamicSharedMemorySize, SM_NN);
    cudaFuncSetAttribute(gemm_k<128,128,32,64,32,false,2>, cudaFuncAttributeMaxDynamicSharedMemorySize, SM_NN);
    cudaFuncSetAttribute(gemm_k<128,128,32,64,32,false,3>, cudaFuncAttributeMaxDynamicSharedMemorySize, SM_NN);
    cudaFuncSetAttribute(gemm_k<128,128,32,64,32,true, 4>, cudaFuncAttributeMaxDynamicSharedMemorySize, SM_NT);
    cudaFuncSetAttribute(gemm_k<128, 64,32,32,32,false,0>, cudaFuncAttributeMaxDynamicSharedMemorySize, SM_PV);

    // 1) LN1
    ln_kernel<<<M, 256>>>(x, ln1g, ln1b, x1);

    // 2) QKV projections: [M,1024] @ [1024,1024] + bias
    {
        GemmP p{};
        p.lda = DMODEL; p.ldb = DMODEL; p.ldc = DMODEL; p.K = DMODEL; p.H = 1;
        dim3 grid(DMODEL / 128, M / 128, 1);
        p.A = x1; p.B = Wq; p.bias = bq; p.C = q;
        gemm_k<128,128,32,64,32,false,1><<<grid, 256, SM_NN>>>(p);
        p.B = Wk; p.bias = bk; p.C = k;
        gemm_k<128,128,32,64,32,false,1><<<grid, 256, SM_NN>>>(p);
        p.B = Wv; p.bias = bv; p.C = v;
        gemm_k<128,128,32,64,32,false,1><<<grid, 256, SM_NN>>>(p);
    }

    // 3) scores = Q @ K^T / 8, masked   (batched over B*H)
    {
        GemmP p{};
        p.A = q; p.B = k; p.C = s;
        p.lda = DMODEL; p.ldb = DMODEL; p.ldc = SEQ; p.K = DKH; p.H = NHEADS;
        p.sAo = (long long)SEQ * DMODEL; p.sAi = DKH;
        p.sBo = (long long)SEQ * DMODEL; p.sBi = DKH;
        p.sCo = (long long)NHEADS * SEQ * SEQ; p.sCi = (long long)SEQ * SEQ;
        p.mask = em; p.maskL = SEQ; p.scale = 0.125f;
        gemm_k<128,128,32,64,32,true,4><<<dim3(SEQ / 128, SEQ / 128, Bb * NHEADS), 256, SM_NT>>>(p);
    }

    // 4) softmax over rows of scores
    softmax_kernel<<<Bb * NHEADS * SEQ, 256>>>(s);

    // 5) attn = P @ V   (batched over B*H), write in [B*L, H*Dk] layout
    {
        GemmP p{};
        p.A = s; p.B = v; p.C = at;
        p.lda = SEQ; p.ldb = DMODEL; p.ldc = DMODEL; p.K = SEQ; p.H = NHEADS;
        p.sAo = (long long)NHEADS * SEQ * SEQ; p.sAi = (long long)SEQ * SEQ;
        p.sBo = (long long)SEQ * DMODEL; p.sBi = DKH;
        p.sCo = (long long)SEQ * DMODEL; p.sCi = DKH;
        gemm_k<128,64,32,32,32,false,0><<<dim3(1, SEQ / 128, Bb * NHEADS), 256, SM_PV>>>(p);
    }

    // 6) x = x + attn @ Wo + bo   -> d_out
    {
        GemmP p{};
        p.A = at; p.B = Wo; p.bias = bo; p.res = x; p.C = out;
        p.lda = DMODEL; p.ldb = DMODEL; p.ldc = DMODEL; p.K = DMODEL; p.H = 1;
        gemm_k<128,128,32,64,32,false,3><<<dim3(DMODEL / 128, M / 128, 1), 256, SM_NN>>>(p);
    }

    // 7) LN2 -> x2 (reuse x1)
    ln_kernel<<<M, 256>>>(out, ln2g, ln2b, x1);

    // 8) h = relu(x2 @ W1 + b1)
    {
        GemmP p{};
        p.A = x1; p.B = W1; p.bias = b1; p.C = h;
        p.lda = DMODEL; p.ldb = DFF; p.ldc = DFF; p.K = DMODEL; p.H = 1;
        gemm_k<128,128,32,64,32,false,2><<<dim3(DFF / 128, M / 128, 1), 256, SM_NN>>>(p);
    }

    // 9) out = out + h @ W2 + b2
    {
        GemmP p{};
        p.A = h; p.B = W2; p.bias = b2; p.res = out; p.C = out;
        p.lda = DFF; p.ldb = DMODEL; p.ldc = DMODEL; p.K = DFF; p.H = 1;
        gemm_k<128,128,32,64,32,false,3><<<dim3(DMODEL / 128, M / 128, 1), 256, SM_NN>>>(p);
    }
}